// round 9
// baseline (speedup 1.0000x reference)
#include <cuda_runtime.h>
#include <cuda_fp16.h>
#include <math.h>
#include <stdint.h>

#define Bsz   4096
#define OBS   1024
#define EOUT  512
#define H1D   2048
#define H2D   2048

// fp16 scratch stored as uint32 half2 words
__device__ uint32_t t_obs[Bsz * OBS / 2];
__device__ uint32_t t_We [EOUT * OBS / 2];
__device__ uint32_t t_dW [OBS * EOUT / 2];
__device__ uint32_t t_W1 [H1D * OBS / 2];
__device__ uint32_t t_W2 [H2D * H1D / 2];
__device__ uint32_t t_e  [Bsz * EOUT / 2];
__device__ uint32_t t_sa [Bsz * OBS / 2];
__device__ uint32_t t_h1 [Bsz * H1D / 2];
__device__ uint32_t t_h2 [Bsz * H2D / 2];
__device__ float    g_db [OBS];

__device__ __forceinline__ uint32_t pack_h2(float x, float y) {
    __half2 h = __floats2half2_rn(x, y);
    return *(uint32_t*)&h;
}
__device__ __forceinline__ float tanh_ap(float x) {
    float y;
    asm("tanh.approx.f32 %0, %1;" : "=f"(y) : "f"(x));
    return y;
}
__device__ __forceinline__ float sigmoid_ap(float x) {
    return 0.5f + 0.5f * tanh_ap(0.5f * x);
}
__device__ __forceinline__ uint32_t smem_u32(const void* p) {
    uint32_t a;
    asm("{ .reg .u64 t; cvta.to.shared.u64 t, %1; cvt.u32.u64 %0, t; }"
        : "=r"(a) : "l"(p));
    return a;
}

// ---------------------------------------------------------------------------
// prep: convert obs/We/W1/W2 to fp16; fold softmax -> sigmoid diff (fp16 dW)
// ---------------------------------------------------------------------------
__global__ void prep_all(const float* __restrict__ obs, const float* __restrict__ We,
                         const float* __restrict__ W1,  const float* __restrict__ W2,
                         const float* __restrict__ attn_W, const float* __restrict__ attn_b,
                         float* __restrict__ db) {
    const int Q0 = (Bsz * OBS) / 4, Q1 = (EOUT * OBS) / 4, Q2 = (H1D * OBS) / 4,
              Q3 = (H2D * H1D) / 4, Q4 = (OBS * EOUT) / 4;
    const int total = Q0 + Q1 + Q2 + Q3 + Q4;
    int tid0 = blockIdx.x * blockDim.x + threadIdx.x;
    for (int i = tid0; i < total; i += gridDim.x * blockDim.x) {
        int j = i;
        if (j < Q0) {
            float4 v = ((const float4*)obs)[j];
            t_obs[2*j]   = pack_h2(v.x, v.y);
            t_obs[2*j+1] = pack_h2(v.z, v.w);
        } else if ((j -= Q0) < Q1) {
            float4 v = ((const float4*)We)[j];
            t_We[2*j]   = pack_h2(v.x, v.y);
            t_We[2*j+1] = pack_h2(v.z, v.w);
        } else if ((j -= Q1) < Q2) {
            float4 v = ((const float4*)W1)[j];
            t_W1[2*j]   = pack_h2(v.x, v.y);
            t_W1[2*j+1] = pack_h2(v.z, v.w);
        } else if ((j -= Q2) < Q3) {
            float4 v = ((const float4*)W2)[j];
            t_W2[2*j]   = pack_h2(v.x, v.y);
            t_W2[2*j+1] = pack_h2(v.z, v.w);
        } else {
            j -= Q3;
            float4 p = ((const float4*)attn_W)[2 * j];
            float4 q = ((const float4*)attn_W)[2 * j + 1];
            t_dW[2*j]   = pack_h2(p.y - p.x, p.w - p.z);
            t_dW[2*j+1] = pack_h2(q.y - q.x, q.w - q.z);
        }
    }
    if (tid0 < OBS) db[tid0] = attn_b[2 * tid0 + 1] - attn_b[2 * tid0];
}

// ---------------------------------------------------------------------------
// fp16 mma.sync GEMM (m16n8k16), persistent CTAs, cp.async 3-stage pipeline,
// ldmatrix.x4 fragment loads, register double buffering.
//   128 threads = 2x2 warps, warp tile 64x64, CTA tile 128x128, BK=64 halves.
//   Swizzle: 16B chunk c of row r stored at chunk c^(r&7).
// ACT 0: tanh -> fp16 out. ACT 1: sigmoid -> fp32 C, C2 = h2(obsp*sig).
// ---------------------------------------------------------------------------
template <int ACT>
__global__ __launch_bounds__(128, 2)
void mm_fp16(const uint32_t* __restrict__ A, const uint32_t* __restrict__ B,
             const float* __restrict__ bias,
             void* __restrict__ Cv, uint32_t* __restrict__ C2,
             const float* __restrict__ obsp,
             int M, int N, int K) {
    extern __shared__ uint32_t sm[];   // 3 * 8192 words (A 4096 + B 4096 each)
    const int t    = threadIdx.x;
    const int lane = t & 31;
    const int wid  = t >> 5;           // 0..3
    const int wm   = wid & 1;
    const int wn   = wid >> 1;         // 0..1
    const int qr   = lane >> 2;
    const int qc   = lane & 3;
    const int Kw   = K >> 1;           // words per row

    // ldmatrix per-lane geometry
    const int l7 = lane & 7;
    const int g  = lane >> 3;
    const int rowA = (g & 1) << 3;
    const int chA  = g >> 1;
    const int rowB = (g >> 1) << 3;
    const int chB  = g & 1;

    // cp.async mapping: 128 thr; thread covers rows r+16i (i=0..7), chunk q
    const int r = t >> 3;              // 0..15
    const int q = t & 7;
    const uint32_t smB = smem_u32(sm);
    const uint32_t sw = (uint32_t)((q ^ (r & 7)) << 2);   // row-low bits invariant under +16
    const uint32_t aDst0 = (uint32_t)r * 32 + sw;         // + i*512
    const uint32_t bDst0 = 4096u + (uint32_t)r * 32 + sw;
    const int Kw16 = Kw << 4;          // 16 rows worth of words

    const int MT = M >> 7, NT = N >> 7, ntiles = MT * NT;
    const int NC = K >> 6;

    for (int tile = blockIdx.x; tile < ntiles; tile += gridDim.x) {
        const int m0 = (tile % MT) << 7;   // m-fastest: concurrent CTAs share B
        const int n0 = (tile / MT) << 7;

        const uint32_t* aBase = A + (size_t)(m0 + r) * Kw + (q << 2);
        const uint32_t* bBase = B + (size_t)(n0 + r) * Kw + (q << 2);

#define ISSUE_CHUNK(c)                                                        \
    do {                                                                      \
        uint32_t so = (uint32_t)((c) % 3) * 8192u;                            \
        _Pragma("unroll")                                                     \
        for (int i = 0; i < 8; ++i) {                                         \
            uint32_t da = smB + ((so + aDst0 + (uint32_t)i * 512u) << 2);     \
            asm volatile("cp.async.cg.shared.global [%0], [%1], 16;"          \
                         :: "r"(da), "l"(aBase + i * Kw16 + (c) * 32)         \
                         : "memory");                                         \
        }                                                                     \
        _Pragma("unroll")                                                     \
        for (int i = 0; i < 8; ++i) {                                         \
            uint32_t dbp = smB + ((so + bDst0 + (uint32_t)i * 512u) << 2);    \
            asm volatile("cp.async.cg.shared.global [%0], [%1], 16;"          \
                         :: "r"(dbp), "l"(bBase + i * Kw16 + (c) * 32)        \
                         : "memory");                                         \
        }                                                                     \
        asm volatile("cp.async.commit_group;" ::: "memory");                  \
    } while (0)

// A fragment: r0..r3 = (m,klo),(m+8,klo),(m,khi),(m+8,khi)
#define LDA(ks, mt, buf)                                                      \
    do {                                                                      \
        uint32_t R_ = (uint32_t)(wm * 64 + (mt) * 16 + l7 + rowA);            \
        uint32_t C_ = (uint32_t)(((((ks) << 1) | chA) ^ l7) << 2);            \
        uint32_t ad_ = smB + ((bA + R_ * 32u + C_) << 2);                     \
        asm volatile("ldmatrix.sync.aligned.m8n8.x4.shared.b16 "              \
                     "{%0,%1,%2,%3}, [%4];"                                   \
                     : "=r"(af[buf][0]), "=r"(af[buf][1]),                    \
                       "=r"(af[buf][2]), "=r"(af[buf][3])                     \
                     : "r"(ad_));                                             \
    } while (0)

// B pair (nt=2p,2p+1): r0..r3 = (n,klo),(n,khi),(n+8,klo),(n+8,khi)
#define LDB1(ks, p, buf)                                                      \
    do {                                                                      \
        uint32_t R_ = (uint32_t)(wn * 64 + (p) * 16 + l7 + rowB);             \
        uint32_t C_ = (uint32_t)(((((ks) << 1) | chB) ^ l7) << 2);            \
        uint32_t ad_ = smB + ((bB + R_ * 32u + C_) << 2);                     \
        asm volatile("ldmatrix.sync.aligned.m8n8.x4.shared.b16 "              \
                     "{%0,%1,%2,%3}, [%4];"                                   \
                     : "=r"(bf[buf][2*(p)][0]),   "=r"(bf[buf][2*(p)][1]),    \
                       "=r"(bf[buf][2*(p)+1][0]), "=r"(bf[buf][2*(p)+1][1])   \
                     : "r"(ad_));                                             \
    } while (0)

#define LDB(ks, buf) \
    do { LDB1(ks, 0, buf); LDB1(ks, 1, buf); LDB1(ks, 2, buf); LDB1(ks, 3, buf); } while (0)

        float acc[4][8][4];
#pragma unroll
        for (int i = 0; i < 4; ++i)
#pragma unroll
            for (int j = 0; j < 8; ++j)
#pragma unroll
                for (int k = 0; k < 4; ++k) acc[i][j][k] = 0.0f;

        ISSUE_CHUNK(0);
        ISSUE_CHUNK(1);

        for (int c = 0; c < NC; ++c) {
            if (c + 1 < NC)
                asm volatile("cp.async.wait_group 1;" ::: "memory");
            else
                asm volatile("cp.async.wait_group 0;" ::: "memory");
            __syncthreads();

            const uint32_t bA = (uint32_t)(c % 3) * 8192u;
            const uint32_t bB = bA + 4096u;

            uint32_t bf[2][8][2];
            uint32_t af[2][4];

            LDB(0, 0);
            LDA(0, 0, 0);
            if (c + 2 < NC) ISSUE_CHUNK(c + 2);

#pragma unroll
            for (int ks = 0; ks < 4; ++ks) {
                if (ks < 3) LDB(ks + 1, (ks + 1) & 1);
#pragma unroll
                for (int mt = 0; mt < 4; ++mt) {
                    if (mt < 3)      LDA(ks, mt + 1, (mt + 1) & 1);
                    else if (ks < 3) LDA(ks + 1, 0, 0);
                    const uint32_t* a = af[mt & 1];
#pragma unroll
                    for (int nt = 0; nt < 8; ++nt) {
                        asm volatile(
                            "mma.sync.aligned.m16n8k16.row.col.f32.f16.f16.f32 "
                            "{%0,%1,%2,%3}, {%4,%5,%6,%7}, {%8,%9}, {%0,%1,%2,%3};"
                            : "+f"(acc[mt][nt][0]), "+f"(acc[mt][nt][1]),
                              "+f"(acc[mt][nt][2]), "+f"(acc[mt][nt][3])
                            : "r"(a[0]), "r"(a[1]), "r"(a[2]), "r"(a[3]),
                              "r"(bf[ks & 1][nt][0]), "r"(bf[ks & 1][nt][1]));
                    }
                }
            }
            // ensure all fragment reads of this stage are done before it is
            // overwritten two iterations later (stage distance 3 w/ 1 sync/iter
            // keeps this safe; sync at top of next iter covers it)
        }
#undef ISSUE_CHUNK
#undef LDA
#undef LDB1
#undef LDB

        // epilogue
        const int Nw = N >> 1;
#pragma unroll
        for (int mt = 0; mt < 4; ++mt) {
            const int m = m0 + wm * 64 + mt * 16 + qr;
#pragma unroll
            for (int nt = 0; nt < 8; ++nt) {
                const int n = n0 + wn * 64 + nt * 8 + 2 * qc;
                const float bx = bias[n], by = bias[n + 1];
#pragma unroll
                for (int h = 0; h < 2; ++h) {
                    const int mm = m + 8 * h;
                    float vx = acc[mt][nt][2 * h + 0] + bx;
                    float vy = acc[mt][nt][2 * h + 1] + by;
                    if (ACT == 0) {
                        vx = tanh_ap(vx); vy = tanh_ap(vy);
                        ((uint32_t*)Cv)[(size_t)mm * Nw + (n >> 1)] = pack_h2(vx, vy);
                    } else {
                        vx = sigmoid_ap(vx); vy = sigmoid_ap(vy);
                        *(float2*)((float*)Cv + (size_t)mm * N + n) = make_float2(vx, vy);
                        float2 ob = *(const float2*)(obsp + (size_t)mm * N + n);
                        C2[(size_t)mm * Nw + (n >> 1)] = pack_h2(ob.x * vx, ob.y * vy);
                    }
                }
            }
        }
        __syncthreads();   // smem reuse safety across persistent tiles
    }
}

// ---------------------------------------------------------------------------
// GEMV: v[b] = dot(h2[b,:], W3) + b3   (h2 fp16 half2 words)
// ---------------------------------------------------------------------------
__global__ __launch_bounds__(256)
void gemv_kernel(const uint32_t* __restrict__ H, const float* __restrict__ W3,
                 const float* __restrict__ b3, float* __restrict__ out) {
    __shared__ float red[8];
    int b = blockIdx.x;
    const uint32_t* row = H + (size_t)b * (H2D / 2);
    float s = 0.0f;
    for (int w = threadIdx.x; w < H2D / 2; w += 256) {
        __half2 hv = *(const __half2*)(row + w);
        float2 f = __half22float2(hv);
        s = fmaf(f.x, W3[2 * w], s);
        s = fmaf(f.y, W3[2 * w + 1], s);
    }
    for (int off = 16; off > 0; off >>= 1)
        s += __shfl_down_sync(0xffffffffu, s, off);
    if ((threadIdx.x & 31) == 0) red[threadIdx.x >> 5] = s;
    __syncthreads();
    if (threadIdx.x == 0) {
        float tot = 0.0f;
#pragma unroll
        for (int w = 0; w < 8; w++) tot += red[w];
        out[b] = tot + b3[0];
    }
}

// ---------------------------------------------------------------------------
// Launch
// ---------------------------------------------------------------------------
extern "C" void kernel_launch(void* const* d_in, const int* in_sizes, int n_in,
                              void* d_out, int out_size) {
    const float* obs    = (const float*)d_in[0];
    const float* We     = (const float*)d_in[1];
    const float* be     = (const float*)d_in[2];
    const float* attn_W = (const float*)d_in[3];
    const float* attn_b = (const float*)d_in[4];
    const float* W1     = (const float*)d_in[5];
    const float* b1     = (const float*)d_in[6];
    const float* W2     = (const float*)d_in[7];
    const float* b2     = (const float*)d_in[8];
    const float* W3     = (const float*)d_in[9];
    const float* b3     = (const float*)d_in[10];

    float* out_v    = (float*)d_out;
    float* out_attn = (float*)d_out + Bsz;

    uint32_t *pobs, *pWe, *pdW, *pW1, *pW2, *pe, *psa, *ph1, *ph2;
    float* pdb;
    cudaGetSymbolAddress((void**)&pobs, t_obs);
    cudaGetSymbolAddress((void**)&pWe,  t_We);
    cudaGetSymbolAddress((void**)&pdW,  t_dW);
    cudaGetSymbolAddress((void**)&pW1,  t_W1);
    cudaGetSymbolAddress((void**)&pW2,  t_W2);
    cudaGetSymbolAddress((void**)&pe,   t_e);
    cudaGetSymbolAddress((void**)&psa,  t_sa);
    cudaGetSymbolAddress((void**)&ph1,  t_h1);
    cudaGetSymbolAddress((void**)&ph2,  t_h2);
    cudaGetSymbolAddress((void**)&pdb,  g_db);

    const int SMEM = 3 * 8192 * 4;   // 96 KB
    cudaFuncSetAttribute(mm_fp16<0>, cudaFuncAttributeMaxDynamicSharedMemorySize, SMEM);
    cudaFuncSetAttribute(mm_fp16<1>, cudaFuncAttributeMaxDynamicSharedMemorySize, SMEM);

    const int PGRID = 2 * 148;       // persistent grid: 2 CTAs per SM

    // 1) convert weights/inputs to fp16; fold softmax
    prep_all<<<2048, 256>>>(obs, We, W1, W2, attn_W, attn_b, pdb);

    // 2) e = tanh(obs @ We^T + be)  -> fp16        [4096,512]  K=1024
    mm_fp16<0><<<PGRID, 128, SMEM>>>(pobs, pWe, be, pe, nullptr, nullptr,
                                     Bsz, EOUT, OBS);

    // 3) att = sigmoid(e @ dW^T + db) -> fp32 out; sa = fp16(obs*att)
    mm_fp16<1><<<PGRID, 128, SMEM>>>(pe, pdW, pdb, out_attn, psa, obs,
                                     Bsz, OBS, EOUT);

    // 4) h1 = tanh(sa @ W1^T + b1) -> fp16         [4096,2048] K=1024
    mm_fp16<0><<<PGRID, 128, SMEM>>>(psa, pW1, b1, ph1, nullptr, nullptr,
                                     Bsz, H1D, OBS);

    // 5) h2 = tanh(h1 @ W2^T + b2) -> fp16         [4096,2048] K=2048
    mm_fp16<0><<<PGRID, 128, SMEM>>>(ph1, pW2, b2, ph2, nullptr, nullptr,
                                     Bsz, H2D, H1D);

    // 6) v = h2 @ W3^T + b3                        [4096]
    gemv_kernel<<<Bsz, 256>>>(ph2, W3, b3, out_v);
}

// round 10
// speedup vs baseline: 1.0481x; 1.0481x over previous
#include <cuda_runtime.h>
#include <cuda_fp16.h>
#include <math.h>
#include <stdint.h>

#define Bsz   4096
#define OBS   1024
#define EOUT  512
#define H1D   2048
#define H2D   2048

// fp16 scratch stored as uint32 half2 words
__device__ uint32_t t_obs[Bsz * OBS / 2];
__device__ uint32_t t_We [EOUT * OBS / 2];
__device__ uint32_t t_dW [OBS * EOUT / 2];
__device__ uint32_t t_W1 [H1D * OBS / 2];
__device__ uint32_t t_W2 [H2D * H1D / 2];
__device__ uint32_t t_e  [Bsz * EOUT / 2];
__device__ uint32_t t_sa [Bsz * OBS / 2];
__device__ uint32_t t_h1 [Bsz * H1D / 2];
__device__ float    g_db [OBS];

__device__ __forceinline__ uint32_t pack_h2(float x, float y) {
    __half2 h = __floats2half2_rn(x, y);
    return *(uint32_t*)&h;
}
__device__ __forceinline__ float tanh_ap(float x) {
    float y;
    asm("tanh.approx.f32 %0, %1;" : "=f"(y) : "f"(x));
    return y;
}
__device__ __forceinline__ float sigmoid_ap(float x) {
    return 0.5f + 0.5f * tanh_ap(0.5f * x);
}
__device__ __forceinline__ uint32_t smem_u32(const void* p) {
    uint32_t a;
    asm("{ .reg .u64 t; cvta.to.shared.u64 t, %1; cvt.u32.u64 %0, t; }"
        : "=r"(a) : "l"(p));
    return a;
}

// ---------------------------------------------------------------------------
// prep_light: convert obs/We/dW to fp16, fold softmax bias, seed out_v = b3
// ---------------------------------------------------------------------------
__global__ void prep_light(const float* __restrict__ obs, const float* __restrict__ We,
                           const float* __restrict__ attn_W, const float* __restrict__ attn_b,
                           const float* __restrict__ b3,
                           float* __restrict__ db, float* __restrict__ out_v) {
    const int Q0 = (Bsz * OBS) / 4, Q1 = (EOUT * OBS) / 4, Q4 = (OBS * EOUT) / 4;
    const int total = Q0 + Q1 + Q4;
    int tid0 = blockIdx.x * blockDim.x + threadIdx.x;
    for (int i = tid0; i < total; i += gridDim.x * blockDim.x) {
        int j = i;
        if (j < Q0) {
            float4 v = ((const float4*)obs)[j];
            t_obs[2*j]   = pack_h2(v.x, v.y);
            t_obs[2*j+1] = pack_h2(v.z, v.w);
        } else if ((j -= Q0) < Q1) {
            float4 v = ((const float4*)We)[j];
            t_We[2*j]   = pack_h2(v.x, v.y);
            t_We[2*j+1] = pack_h2(v.z, v.w);
        } else {
            j -= Q1;
            float4 p = ((const float4*)attn_W)[2 * j];
            float4 q = ((const float4*)attn_W)[2 * j + 1];
            t_dW[2*j]   = pack_h2(p.y - p.x, p.w - p.z);
            t_dW[2*j+1] = pack_h2(q.y - q.x, q.w - q.z);
        }
    }
    if (tid0 < OBS)  db[tid0] = attn_b[2 * tid0 + 1] - attn_b[2 * tid0];
    if (tid0 < Bsz)  out_v[tid0] = b3[0];
}

// ---------------------------------------------------------------------------
// prep_heavy: convert W1/W2 to fp16 (runs on side stream, overlaps G2/G3)
// ---------------------------------------------------------------------------
__global__ void prep_heavy(const float* __restrict__ W1, const float* __restrict__ W2) {
    const int Q2 = (H1D * OBS) / 4, Q3 = (H2D * H1D) / 4;
    const int total = Q2 + Q3;
    int tid0 = blockIdx.x * blockDim.x + threadIdx.x;
    for (int i = tid0; i < total; i += gridDim.x * blockDim.x) {
        int j = i;
        if (j < Q2) {
            float4 v = ((const float4*)W1)[j];
            t_W1[2*j]   = pack_h2(v.x, v.y);
            t_W1[2*j+1] = pack_h2(v.z, v.w);
        } else {
            j -= Q2;
            float4 v = ((const float4*)W2)[j];
            t_W2[2*j]   = pack_h2(v.x, v.y);
            t_W2[2*j+1] = pack_h2(v.z, v.w);
        }
    }
}

// ---------------------------------------------------------------------------
// fp16 mma.sync GEMM (m16n8k16), persistent CTAs, cp.async 3-stage pipeline,
// ldmatrix.x4 fragment loads, register double buffering.
//   128 threads = 2x2 warps, warp tile 64x64, CTA tile 128x128, BK=64 halves.
// ACT 0: tanh -> fp16 out (Cv).
// ACT 1: sigmoid -> fp32 C (Cv), C2 = h2(obsp * sig).
// ACT 2: tanh, NO tile store; fused v-reduction: Cv = out_v (fp32, atomicAdd),
//        obsp = W3 (fp32 weights).
// ---------------------------------------------------------------------------
template <int ACT>
__global__ __launch_bounds__(128, 2)
void mm_fp16(const uint32_t* __restrict__ A, const uint32_t* __restrict__ B,
             const float* __restrict__ bias,
             void* __restrict__ Cv, uint32_t* __restrict__ C2,
             const float* __restrict__ obsp,
             int M, int N, int K) {
    extern __shared__ uint32_t sm[];   // 3 * 8192 words (A 4096 + B 4096 each)
    const int t    = threadIdx.x;
    const int lane = t & 31;
    const int wid  = t >> 5;
    const int wm   = wid & 1;
    const int wn   = wid >> 1;
    const int qr   = lane >> 2;
    const int qc   = lane & 3;
    const int Kw   = K >> 1;

    const int l7 = lane & 7;
    const int g  = lane >> 3;
    const int rowA = (g & 1) << 3;
    const int chA  = g >> 1;
    const int rowB = (g >> 1) << 3;
    const int chB  = g & 1;

    const int r = t >> 3;              // 0..15
    const int q = t & 7;
    const uint32_t smB = smem_u32(sm);
    const uint32_t sw = (uint32_t)((q ^ (r & 7)) << 2);
    const uint32_t aDst0 = (uint32_t)r * 32 + sw;
    const uint32_t bDst0 = 4096u + (uint32_t)r * 32 + sw;
    const int Kw16 = Kw << 4;

    const int MT = M >> 7, NT = N >> 7, ntiles = MT * NT;
    const int NC = K >> 6;

    for (int tile = blockIdx.x; tile < ntiles; tile += gridDim.x) {
        const int m0 = (tile % MT) << 7;
        const int n0 = (tile / MT) << 7;

        const uint32_t* aBase = A + (size_t)(m0 + r) * Kw + (q << 2);
        const uint32_t* bBase = B + (size_t)(n0 + r) * Kw + (q << 2);

#define ISSUE_CHUNK(c)                                                        \
    do {                                                                      \
        uint32_t so = (uint32_t)((c) % 3) * 8192u;                            \
        _Pragma("unroll")                                                     \
        for (int i = 0; i < 8; ++i) {                                         \
            uint32_t da = smB + ((so + aDst0 + (uint32_t)i * 512u) << 2);     \
            asm volatile("cp.async.cg.shared.global [%0], [%1], 16;"          \
                         :: "r"(da), "l"(aBase + i * Kw16 + (c) * 32)         \
                         : "memory");                                         \
        }                                                                     \
        _Pragma("unroll")                                                     \
        for (int i = 0; i < 8; ++i) {                                         \
            uint32_t dbp = smB + ((so + bDst0 + (uint32_t)i * 512u) << 2);    \
            asm volatile("cp.async.cg.shared.global [%0], [%1], 16;"          \
                         :: "r"(dbp), "l"(bBase + i * Kw16 + (c) * 32)        \
                         : "memory");                                         \
        }                                                                     \
        asm volatile("cp.async.commit_group;" ::: "memory");                  \
    } while (0)

#define LDA(ks, mt, buf)                                                      \
    do {                                                                      \
        uint32_t R_ = (uint32_t)(wm * 64 + (mt) * 16 + l7 + rowA);            \
        uint32_t C_ = (uint32_t)(((((ks) << 1) | chA) ^ l7) << 2);            \
        uint32_t ad_ = smB + ((bA + R_ * 32u + C_) << 2);                     \
        asm volatile("ldmatrix.sync.aligned.m8n8.x4.shared.b16 "              \
                     "{%0,%1,%2,%3}, [%4];"                                   \
                     : "=r"(af[buf][0]), "=r"(af[buf][1]),                    \
                       "=r"(af[buf][2]), "=r"(af[buf][3])                     \
                     : "r"(ad_));                                             \
    } while (0)

#define LDB1(ks, p, buf)                                                      \
    do {                                                                      \
        uint32_t R_ = (uint32_t)(wn * 64 + (p) * 16 + l7 + rowB);             \
        uint32_t C_ = (uint32_t)(((((ks) << 1) | chB) ^ l7) << 2);            \
        uint32_t ad_ = smB + ((bB + R_ * 32u + C_) << 2);                     \
        asm volatile("ldmatrix.sync.aligned.m8n8.x4.shared.b16 "              \
                     "{%0,%1,%2,%3}, [%4];"                                   \
                     : "=r"(bf[buf][2*(p)][0]),   "=r"(bf[buf][2*(p)][1]),    \
                       "=r"(bf[buf][2*(p)+1][0]), "=r"(bf[buf][2*(p)+1][1])   \
                     : "r"(ad_));                                             \
    } while (0)

#define LDB(ks, buf) \
    do { LDB1(ks, 0, buf); LDB1(ks, 1, buf); LDB1(ks, 2, buf); LDB1(ks, 3, buf); } while (0)

        float acc[4][8][4];
#pragma unroll
        for (int i = 0; i < 4; ++i)
#pragma unroll
            for (int j = 0; j < 8; ++j)
#pragma unroll
                for (int k = 0; k < 4; ++k) acc[i][j][k] = 0.0f;

        ISSUE_CHUNK(0);
        ISSUE_CHUNK(1);

        for (int c = 0; c < NC; ++c) {
            if (c + 1 < NC)
                asm volatile("cp.async.wait_group 1;" ::: "memory");
            else
                asm volatile("cp.async.wait_group 0;" ::: "memory");
            __syncthreads();

            const uint32_t bA = (uint32_t)(c % 3) * 8192u;
            const uint32_t bB = bA + 4096u;

            uint32_t bf[2][8][2];
            uint32_t af[2][4];

            LDB(0, 0);
            LDA(0, 0, 0);
            if (c + 2 < NC) ISSUE_CHUNK(c + 2);

#pragma unroll
            for (int ks = 0; ks < 4; ++ks) {
                if (ks < 3) LDB(ks + 1, (ks + 1) & 1);
#pragma unroll
                for (int mt = 0; mt < 4; ++mt) {
                    if (mt < 3)      LDA(ks, mt + 1, (mt + 1) & 1);
                    else if (ks < 3) LDA(ks + 1, 0, 0);
                    const uint32_t* a = af[mt & 1];
#pragma unroll
                    for (int nt = 0; nt < 8; ++nt) {
                        asm volatile(
                            "mma.sync.aligned.m16n8k16.row.col.f32.f16.f16.f32 "
                            "{%0,%1,%2,%3}, {%4,%5,%6,%7}, {%8,%9}, {%0,%1,%2,%3};"
                            : "+f"(acc[mt][nt][0]), "+f"(acc[mt][nt][1]),
                              "+f"(acc[mt][nt][2]), "+f"(acc[mt][nt][3])
                            : "r"(a[0]), "r"(a[1]), "r"(a[2]), "r"(a[3]),
                              "r"(bf[ks & 1][nt][0]), "r"(bf[ks & 1][nt][1]));
                    }
                }
            }
        }
#undef ISSUE_CHUNK
#undef LDA
#undef LDB1
#undef LDB

        // epilogue
        const int Nw = N >> 1;
#pragma unroll
        for (int mt = 0; mt < 4; ++mt) {
            const int m = m0 + wm * 64 + mt * 16 + qr;
            float vsum[2] = {0.0f, 0.0f};
#pragma unroll
            for (int nt = 0; nt < 8; ++nt) {
                const int n = n0 + wn * 64 + nt * 8 + 2 * qc;
                const float bx = bias[n], by = bias[n + 1];
#pragma unroll
                for (int h = 0; h < 2; ++h) {
                    const int mm = m + 8 * h;
                    float vx = acc[mt][nt][2 * h + 0] + bx;
                    float vy = acc[mt][nt][2 * h + 1] + by;
                    if (ACT == 0) {
                        vx = tanh_ap(vx); vy = tanh_ap(vy);
                        ((uint32_t*)Cv)[(size_t)mm * Nw + (n >> 1)] = pack_h2(vx, vy);
                    } else if (ACT == 1) {
                        vx = sigmoid_ap(vx); vy = sigmoid_ap(vy);
                        *(float2*)((float*)Cv + (size_t)mm * N + n) = make_float2(vx, vy);
                        float2 ob = *(const float2*)(obsp + (size_t)mm * N + n);
                        C2[(size_t)mm * Nw + (n >> 1)] = pack_h2(ob.x * vx, ob.y * vy);
                    } else {
                        // fused v-reduction: tanh then dot with W3 (obsp)
                        vx = tanh_ap(vx); vy = tanh_ap(vy);
                        vsum[h] += vx * obsp[n] + vy * obsp[n + 1];
                    }
                }
            }
            if (ACT == 2) {
#pragma unroll
                for (int h = 0; h < 2; ++h) {
                    float s = vsum[h];
                    s += __shfl_xor_sync(0xffffffffu, s, 1);
                    s += __shfl_xor_sync(0xffffffffu, s, 2);
                    if (qc == 0)
                        atomicAdd((float*)Cv + (m + 8 * h), s);
                }
            }
        }
        __syncthreads();   // smem reuse safety across persistent tiles
    }
}

// ---------------------------------------------------------------------------
// Launch
// ---------------------------------------------------------------------------
extern "C" void kernel_launch(void* const* d_in, const int* in_sizes, int n_in,
                              void* d_out, int out_size) {
    const float* obs    = (const float*)d_in[0];
    const float* We     = (const float*)d_in[1];
    const float* be     = (const float*)d_in[2];
    const float* attn_W = (const float*)d_in[3];
    const float* attn_b = (const float*)d_in[4];
    const float* W1     = (const float*)d_in[5];
    const float* b1     = (const float*)d_in[6];
    const float* W2     = (const float*)d_in[7];
    const float* b2     = (const float*)d_in[8];
    const float* W3     = (const float*)d_in[9];
    const float* b3     = (const float*)d_in[10];

    float* out_v    = (float*)d_out;
    float* out_attn = (float*)d_out + Bsz;

    uint32_t *pobs, *pWe, *pdW, *pW1, *pW2, *pe, *psa, *ph1;
    float* pdb;
    cudaGetSymbolAddress((void**)&pobs, t_obs);
    cudaGetSymbolAddress((void**)&pWe,  t_We);
    cudaGetSymbolAddress((void**)&pdW,  t_dW);
    cudaGetSymbolAddress((void**)&pW1,  t_W1);
    cudaGetSymbolAddress((void**)&pW2,  t_W2);
    cudaGetSymbolAddress((void**)&pe,   t_e);
    cudaGetSymbolAddress((void**)&psa,  t_sa);
    cudaGetSymbolAddress((void**)&ph1,  t_h1);
    cudaGetSymbolAddress((void**)&pdb,  g_db);

    const int SMEM = 3 * 8192 * 4;   // 96 KB
    cudaFuncSetAttribute(mm_fp16<0>, cudaFuncAttributeMaxDynamicSharedMemorySize, SMEM);
    cudaFuncSetAttribute(mm_fp16<1>, cudaFuncAttributeMaxDynamicSharedMemorySize, SMEM);
    cudaFuncSetAttribute(mm_fp16<2>, cudaFuncAttributeMaxDynamicSharedMemorySize, SMEM);

    const int PGRID = 2 * 148;       // persistent grid: 2 CTAs per SM

    // Fork heavy weight conversion (W1,W2) onto a side stream to overlap G2/G3
    cudaStream_t sHeavy;
    cudaStreamCreateWithFlags(&sHeavy, cudaStreamNonBlocking);
    cudaEvent_t evFork, evJoin;
    cudaEventCreateWithFlags(&evFork, cudaEventDisableTiming);
    cudaEventCreateWithFlags(&evJoin, cudaEventDisableTiming);

    cudaEventRecord(evFork, 0);
    cudaStreamWaitEvent(sHeavy, evFork, 0);
    prep_heavy<<<1480, 256, 0, sHeavy>>>(W1, W2);
    cudaEventRecord(evJoin, sHeavy);

    // 1) light prep on main stream (obs/We/dW, db, out_v = b3)
    prep_light<<<1024, 256>>>(obs, We, attn_W, attn_b, b3, pdb, out_v);

    // 2) e = tanh(obs @ We^T + be)  -> fp16        [4096,512]  K=1024
    mm_fp16<0><<<PGRID, 128, SMEM>>>(pobs, pWe, be, pe, nullptr, nullptr,
                                     Bsz, EOUT, OBS);

    // 3) att = sigmoid(e @ dW^T + db) -> fp32 out; sa = fp16(obs*att)
    mm_fp16<1><<<PGRID, 128, SMEM>>>(pe, pdW, pdb, out_attn, psa, obs,
                                     Bsz, OBS, EOUT);

    // join: W1/W2 conversion must be done before G4/G5
    cudaStreamWaitEvent(0, evJoin, 0);

    // 4) h1 = tanh(sa @ W1^T + b1) -> fp16         [4096,2048] K=1024
    mm_fp16<0><<<PGRID, 128, SMEM>>>(psa, pW1, b1, ph1, nullptr, nullptr,
                                     Bsz, H1D, OBS);

    // 5) v += rowsum(tanh(h1 @ W2^T + b2) * W3)    fused GEMM+GEMV
    mm_fp16<2><<<PGRID, 128, SMEM>>>(ph1, pW2, b2, out_v, nullptr, W3,
                                     Bsz, H2D, H1D);
}